// round 12
// baseline (speedup 1.0000x reference)
#include <cuda_runtime.h>
#include <cstdint>

// Problem constants
#define BS   32
#define CLS  80
#define HH   128
#define WW   128
#define HW   16384
#define K    100
#define CAND_CAP  3072   // ~40 sigma above expected ~1850 peaks
#define FINAL_CAP 256

// Output layout (fp32, concatenated in reference return order)
#define OFF_SC   0                      // (32,80,100) per-class topk scores
#define OFF_IND  (BS*CLS*K)             // 256000
#define OFF_CLSO (OFF_IND + BS*K)       // 259200
#define OFF_YS   (OFF_CLSO + BS*K)      // 262400
#define OFF_XS   (OFF_YS + BS*K)        // 265600

// Scratch: per-class top-100 flat spatial indices
__device__ int g_idx1[BS * CLS * K];
// Per-batch completion counters (zero-init; reset by consumer -> graph-safe)
__device__ int g_done[BS];

// Inclusive suffix-scan over 256 histogram bins.
// After call: s_scan[p] = sum of s_hist[255-p .. 255]  (suffix(d) = s_scan[255-d]).
__device__ __forceinline__ void suffix_scan_store(const int* s_hist, int* s_scan,
                                                  int* s_red, int tid, int lane, int warp) {
    int incl = s_hist[255 - tid];
    #pragma unroll
    for (int o = 1; o < 32; o <<= 1) {
        int x = __shfl_up_sync(0xFFFFFFFFu, incl, o);
        if (lane >= o) incl += x;
    }
    if (lane == 31) s_red[warp] = incl;
    __syncthreads();
    int off = 0;
    #pragma unroll
    for (int w = 0; w < 8; ++w) off += (w < warp) ? s_red[w] : 0;
    s_scan[tid] = incl + off;
    __syncthreads();
}

// Descending bitonic sort of FINAL_CAP=256 u64 keys, 256 threads.
__device__ __forceinline__ void bitonic_sort_256(unsigned long long* s_final, int tid) {
    #pragma unroll
    for (int k2 = 2; k2 <= FINAL_CAP; k2 <<= 1) {
        for (int j = k2 >> 1; j > 0; j >>= 1) {
            int ixj = tid ^ j;
            if (ixj > tid) {
                bool desc = ((tid & k2) == 0);
                unsigned long long x = s_final[tid], y = s_final[ixj];
                bool sw = desc ? (x < y) : (x > y);
                if (sw) { s_final[tid] = y; s_final[ixj] = x; }
            }
            __syncthreads();
        }
    }
}

__device__ __forceinline__ float4 fmax4(float4 a, float4 b) {
    return make_float4(fmaxf(a.x, b.x), fmaxf(a.y, b.y),
                       fmaxf(a.z, b.z), fmaxf(a.w, b.w));
}

// ---------------------------------------------------------------------------
// Fused kernel: one CTA per (b,c). Warp-wide-row NMS, deferred append with
// integrated round-1 histogram, SoA radix top-100, bitonic-sort emit;
// last CTA of each batch runs the global top-100 inline.
// ---------------------------------------------------------------------------
__global__ void __launch_bounds__(256, 6)
decode_kernel(const float* __restrict__ hm, float* __restrict__ out)
{
    __shared__ unsigned s_pool[2 * CAND_CAP];         // scores | indices (24 KB)
    __shared__ unsigned long long s_final[FINAL_CAP];
    __shared__ int s_hist[256];
    __shared__ int s_scan[256];
    __shared__ int s_red[8];
    __shared__ int s_sel;
    __shared__ int s_ncand, s_nfinal, s_last;

    unsigned* s_sc  = s_pool;             // candidate score bits
    unsigned* s_idx = s_pool + CAND_CAP;  // candidate flat indices

    const int bc   = blockIdx.x;           // 0..2559
    const int b    = bc / CLS;
    const int tid  = threadIdx.x;
    const int lane = tid & 31;
    const int warp = tid >> 5;
    const float* __restrict__ t = hm + (size_t)bc * HW;
    const float NEG = -3.0e38f;

    if (tid == 0) { s_ncand = 0; s_nfinal = 0; }
    s_hist[tid] = 0;                       // round-1 histogram, filled by append
    __syncthreads();

    // --- NMS: warp owns rows [16w, 16w+16); lane owns cols 4l..4l+3 ---------
    const int r0 = warp << 4;
    const float* rowp = t + (size_t)r0 * WW + (lane << 2);

    float4 Bq, pm, Cq;
    if (warp == 0) pm = make_float4(NEG, NEG, NEG, NEG);
    else           pm = *(const float4*)(rowp - WW);
    Bq = *(const float4*)rowp;
    pm = fmax4(pm, Bq);

    unsigned long long pk = 0ULL;          // 16 rows x 4 peak bits

#define NMS_BODY(RR) do {                                                   \
        float4 vm = fmax4(pm, Cq);                                          \
        float Ln = __shfl_up_sync(0xFFFFFFFFu, vm.w, 1);                    \
        float Rn = __shfl_down_sync(0xFFFFFFFFu, vm.x, 1);                  \
        if (lane == 0)  Ln = NEG;                                           \
        if (lane == 31) Rn = NEG;                                           \
        float tL  = fmaxf(Ln, vm.x);                                        \
        float t01 = fmaxf(vm.x, vm.y);                                      \
        float t12 = fmaxf(vm.y, vm.z);                                      \
        float t23 = fmaxf(vm.z, vm.w);                                      \
        unsigned bits =                                                     \
              (unsigned)(fmaxf(tL,  vm.y) == Bq.x)                          \
            | ((unsigned)(fmaxf(t01, vm.z) == Bq.y) << 1)                   \
            | ((unsigned)(fmaxf(t12, vm.w) == Bq.z) << 2)                   \
            | ((unsigned)(fmaxf(t23, Rn)   == Bq.w) << 3);                  \
        pk |= (unsigned long long)bits << ((RR) << 2);                      \
        pm = fmax4(Bq, Cq);                                                 \
        Bq = Cq;                                                            \
    } while (0)

    // rows 0..14: next row always in-bounds (r0+15 <= 127)
    #pragma unroll 5
    for (int rr = 0; rr < 15; ++rr) {
        Cq = *(const float4*)(rowp + WW);
        rowp += WW;
        NMS_BODY(rr);
    }
    // row 15: next row exists only for warps 0..6 (warp-uniform branch)
    if (warp < 7) Cq = *(const float4*)(rowp + WW);
    else          Cq = make_float4(NEG, NEG, NEG, NEG);
    NMS_BODY(15);
#undef NMS_BODY

    // --- One deferred append per thread (+ round-1 histogram) ---------------
    {
        int n = __popcll(pk);
        int incl = n;
        #pragma unroll
        for (int o = 1; o < 32; o <<= 1) {
            int x = __shfl_up_sync(0xFFFFFFFFu, incl, o);
            if (lane >= o) incl += x;
        }
        int wtot = __shfl_sync(0xFFFFFFFFu, incl, 31);
        int base = 0;
        if (lane == 31 && wtot) base = atomicAdd(&s_ncand, wtot);
        base = __shfl_sync(0xFFFFFFFFu, base, 31);
        int pos = base + incl - n;

        const int cbase = r0 * WW + (lane << 2);
        unsigned long long m = pk;
        while (m) {
            int bit = __ffsll((long long)m) - 1;
            m &= m - 1ULL;
            int idx = cbase + ((bit >> 2) * WW) + (bit & 3);
            unsigned vb = __float_as_uint(__ldg(&t[idx]));
            if (pos < CAND_CAP) {
                s_sc[pos]  = vb;
                s_idx[pos] = (unsigned)idx;
                atomicAdd(&s_hist[vb >> 24], 1);
            }
            pos++;
        }
    }
    __syncthreads();
    int ncand = min(s_ncand, CAND_CAP);

    // --- Pathological fallback: <100 peaks -> append zero-score non-peaks ---
    if (ncand < K) {
        int idx = tid;                     // first 256 cells contain the 100
        int r = idx >> 7, c = idx & (WW - 1);
        float v = t[idx];
        float mval = v;
        for (int dr = -1; dr <= 1; ++dr)
            for (int dc = -1; dc <= 1; ++dc) {
                int rr2 = r + dr, cc = c + dc;
                if (rr2 >= 0 && rr2 < HH && cc >= 0 && cc < WW)
                    mval = fmaxf(mval, t[rr2 * WW + cc]);
            }
        if (mval != v) {   // suppressed: value 0 after keep-mask
            int p = atomicAdd(&s_ncand, 1);
            if (p < CAND_CAP) {
                s_sc[p]  = 0u;
                s_idx[p] = (unsigned)idx;
                atomicAdd(&s_hist[0], 1);
            }
        }
        __syncthreads();
        ncand = min(s_ncand, CAND_CAP);
    }

    // --- Radix-select on u32 score: floor Ts, count(>=Ts) in [K, FINAL_CAP] -
    unsigned Ts;
    {
        int need = K;
        int total_above = 0;
        unsigned prefix = 0;
        int shift = 24;                    // round-1 histogram already built
        for (;;) {
            suffix_scan_store(s_hist, s_scan, s_red, tid, lane, warp);
            {
                int d = tid;
                int suf  = s_scan[255 - d];
                int suf1 = (d == 255) ? 0 : s_scan[254 - d];
                if (suf >= need && suf1 < need) s_sel = d;
            }
            __syncthreads();
            int dsel  = s_sel;
            int A     = (dsel == 255) ? 0 : s_scan[254 - dsel];
            int inbin = s_scan[255 - dsel] - A;
            prefix = (prefix << 8) | (unsigned)dsel;
            total_above += A;
            need -= A;
            if (total_above + inbin <= FINAL_CAP || shift == 0) {
                Ts = prefix << shift;
                break;
            }
            shift -= 8;
            __syncthreads();               // protect s_scan/s_sel
            s_hist[tid] = 0;
            __syncthreads();
            for (int i = tid; i < ncand; i += 256) {
                unsigned sb = s_sc[i];
                if ((sb >> (shift + 8)) == prefix)
                    atomicAdd(&s_hist[(sb >> shift) & 255u], 1);
            }
            __syncthreads();
        }
    }
    __syncthreads();

    // --- Collect survivors (<=256) as u64 keys, pad, sort, emit -------------
    for (int i = tid; i < ncand; i += 256) {
        unsigned sb = s_sc[i];
        if (sb >= Ts) {
            int p = atomicAdd(&s_nfinal, 1);
            if (p < FINAL_CAP)
                s_final[p] = ((unsigned long long)sb << 32) | (unsigned)(~s_idx[i]);
        }
    }
    __syncthreads();
    if (tid >= min(s_nfinal, FINAL_CAP)) s_final[tid] = 0ULL;
    __syncthreads();

    bitonic_sort_256(s_final, tid);

    if (tid < K) {
        unsigned long long kk = s_final[tid];
        out[OFF_SC + bc * K + tid] = __uint_as_float((unsigned)(kk >> 32));
        g_idx1[bc * K + tid] = (int)(~(unsigned)kk);
    }

    // --- Batch completion: last CTA of batch b runs stage2 inline -----------
    __threadfence();
    __syncthreads();
    if (tid == 0) {
        int v = atomicAdd(&g_done[b], 1);
        s_last = (v == CLS - 1) ? 1 : 0;
        if (v == CLS - 1) atomicExch(&g_done[b], 0);   // reset for graph replay
    }
    __syncthreads();
    if (!s_last) return;
    __threadfence();

    // ======================= Inline stage 2 for batch b ======================
    const int NC     = CLS * K;                        // 8000
    const int NCACHE = 2 * CAND_CAP;                   // 6144 u32 cache slots
    const float* __restrict__ sc = out + OFF_SC + (size_t)b * NC;

    s_hist[tid] = 0;
    if (tid == 0) s_nfinal = 0;
    __syncthreads();

    // load + round-1 histogram in one pass
    for (int i = tid; i < NC; i += 256) {
        unsigned sb = __float_as_uint(__ldg(&sc[i]));
        if (i < NCACHE) s_pool[i] = sb;
        atomicAdd(&s_hist[sb >> 24], 1);
    }
    __syncthreads();

    unsigned Ts2;
    {
        int need = K;
        int total_above = 0;
        unsigned prefix = 0;
        int shift = 24;
        for (;;) {
            suffix_scan_store(s_hist, s_scan, s_red, tid, lane, warp);
            {
                int d = tid;
                int suf  = s_scan[255 - d];
                int suf1 = (d == 255) ? 0 : s_scan[254 - d];
                if (suf >= need && suf1 < need) s_sel = d;
            }
            __syncthreads();
            int dsel  = s_sel;
            int A     = (dsel == 255) ? 0 : s_scan[254 - dsel];
            int inbin = s_scan[255 - dsel] - A;
            prefix = (prefix << 8) | (unsigned)dsel;
            total_above += A;
            need -= A;
            if (total_above + inbin <= FINAL_CAP || shift == 0) {
                Ts2 = prefix << shift;
                break;
            }
            shift -= 8;
            __syncthreads();
            s_hist[tid] = 0;
            __syncthreads();
            for (int i = tid; i < NC; i += 256) {
                unsigned sb = (i < NCACHE) ? s_pool[i]
                                           : __float_as_uint(__ldg(&sc[i]));
                if ((sb >> (shift + 8)) == prefix)
                    atomicAdd(&s_hist[(sb >> shift) & 255u], 1);
            }
            __syncthreads();
        }
    }
    __syncthreads();

    for (int i = tid; i < NC; i += 256) {
        unsigned sb = (i < NCACHE) ? s_pool[i] : __float_as_uint(__ldg(&sc[i]));
        if (sb >= Ts2) {
            int p = atomicAdd(&s_nfinal, 1);
            if (p < FINAL_CAP)
                s_final[p] = ((unsigned long long)sb << 32) | (unsigned)(~(unsigned)i);
        }
    }
    __syncthreads();
    if (tid >= min(s_nfinal, FINAL_CAP)) s_final[tid] = 0ULL;
    __syncthreads();

    bitonic_sort_256(s_final, tid);

    if (tid < K) {
        unsigned long long kk = s_final[tid];
        int ci     = (int)(~(unsigned)kk);           // combined idx [0,8000)
        int classe = ci / K;
        int flat   = g_idx1[b * NC + ci];
        out[OFF_IND  + b * K + tid] = (float)flat;
        out[OFF_CLSO + b * K + tid] = (float)classe;
        out[OFF_YS   + b * K + tid] = (float)(flat >> 7);   // y = flat / 128
        out[OFF_XS   + b * K + tid] = (float)(flat & 127);  // x = flat % 128
    }
}

// ---------------------------------------------------------------------------
extern "C" void kernel_launch(void* const* d_in, const int* in_sizes, int n_in,
                              void* d_out, int out_size)
{
    const float* hm = (const float*)d_in[0];
    float* out = (float*)d_out;
    decode_kernel<<<BS * CLS, 256>>>(hm, out);
}

// round 13
// speedup vs baseline: 1.1373x; 1.1373x over previous
#include <cuda_runtime.h>
#include <cstdint>

// Problem constants
#define BS   32
#define CLS  80
#define HH   128
#define WW   128
#define HW   16384
#define K    100
#define CAND_CAP  3072   // ~40 sigma above expected ~1850 peaks
#define FINAL_CAP 256

// Output layout (fp32, concatenated in reference return order)
#define OFF_SC   0                      // (32,80,100) per-class topk scores
#define OFF_IND  (BS*CLS*K)             // 256000
#define OFF_CLSO (OFF_IND + BS*K)       // 259200
#define OFF_YS   (OFF_CLSO + BS*K)      // 262400
#define OFF_XS   (OFF_YS + BS*K)        // 265600

// Scratch: per-class top-100 flat spatial indices
__device__ int g_idx1[BS * CLS * K];
// Per-batch completion counters (zero-init; reset by consumer -> graph-safe)
__device__ int g_done[BS];

// Inclusive suffix-scan over 256 histogram bins.
// After call: s_scan[p] = sum of s_hist[255-p .. 255]  (suffix(d) = s_scan[255-d]).
__device__ __forceinline__ void suffix_scan_store(const int* s_hist, int* s_scan,
                                                  int* s_red, int tid, int lane, int warp) {
    int incl = s_hist[255 - tid];
    #pragma unroll
    for (int o = 1; o < 32; o <<= 1) {
        int x = __shfl_up_sync(0xFFFFFFFFu, incl, o);
        if (lane >= o) incl += x;
    }
    if (lane == 31) s_red[warp] = incl;
    __syncthreads();
    int off = 0;
    #pragma unroll
    for (int w = 0; w < 8; ++w) off += (w < warp) ? s_red[w] : 0;
    s_scan[tid] = incl + off;
    __syncthreads();
}

__device__ __forceinline__ float4 fmax4(float4 a, float4 b) {
    return make_float4(fmaxf(a.x, b.x), fmaxf(a.y, b.y),
                       fmaxf(a.z, b.z), fmaxf(a.w, b.w));
}

// ---------------------------------------------------------------------------
// Fused kernel: one CTA per (b,c). Warp-wide-row NMS, deferred append with
// integrated round-1 histogram, SoA radix top-100, rank-emit;
// last CTA of each batch runs the global top-100 inline.
// ---------------------------------------------------------------------------
__global__ void __launch_bounds__(256, 6)
decode_kernel(const float* __restrict__ hm, float* __restrict__ out)
{
    __shared__ unsigned s_pool[2 * CAND_CAP];         // scores | indices (24 KB)
    __shared__ unsigned long long s_final[FINAL_CAP];
    __shared__ int s_hist[256];
    __shared__ int s_scan[256];
    __shared__ int s_red[8];
    __shared__ int s_sel;
    __shared__ int s_ncand, s_nfinal, s_last;

    unsigned* s_sc  = s_pool;             // candidate score bits
    unsigned* s_idx = s_pool + CAND_CAP;  // candidate flat indices

    const int bc   = blockIdx.x;           // 0..2559
    const int b    = bc / CLS;
    const int tid  = threadIdx.x;
    const int lane = tid & 31;
    const int warp = tid >> 5;
    const float* __restrict__ t = hm + (size_t)bc * HW;
    const float NEG = -3.0e38f;

    if (tid == 0) { s_ncand = 0; s_nfinal = 0; }
    s_hist[tid] = 0;                       // round-1 histogram, filled by append
    __syncthreads();

    // --- NMS: warp owns rows [16w, 16w+16); lane owns cols 4l..4l+3 ---------
    const int r0 = warp << 4;
    const float* rowp = t + (size_t)r0 * WW + (lane << 2);

    float4 Bq, pm, Cq;
    if (warp == 0) pm = make_float4(NEG, NEG, NEG, NEG);
    else           pm = *(const float4*)(rowp - WW);
    Bq = *(const float4*)rowp;
    pm = fmax4(pm, Bq);

    unsigned long long pk = 0ULL;          // 16 rows x 4 peak bits

#define NMS_BODY(RR) do {                                                   \
        float4 vm = fmax4(pm, Cq);                                          \
        float Ln = __shfl_up_sync(0xFFFFFFFFu, vm.w, 1);                    \
        float Rn = __shfl_down_sync(0xFFFFFFFFu, vm.x, 1);                  \
        if (lane == 0)  Ln = NEG;                                           \
        if (lane == 31) Rn = NEG;                                           \
        float tL  = fmaxf(Ln, vm.x);                                        \
        float t01 = fmaxf(vm.x, vm.y);                                      \
        float t12 = fmaxf(vm.y, vm.z);                                      \
        float t23 = fmaxf(vm.z, vm.w);                                      \
        unsigned bits =                                                     \
              (unsigned)(fmaxf(tL,  vm.y) == Bq.x)                          \
            | ((unsigned)(fmaxf(t01, vm.z) == Bq.y) << 1)                   \
            | ((unsigned)(fmaxf(t12, vm.w) == Bq.z) << 2)                   \
            | ((unsigned)(fmaxf(t23, Rn)   == Bq.w) << 3);                  \
        pk |= (unsigned long long)bits << ((RR) << 2);                      \
        pm = fmax4(Bq, Cq);                                                 \
        Bq = Cq;                                                            \
    } while (0)

    // rows 0..14: next row always in-bounds (r0+15 <= 127)
    #pragma unroll 5
    for (int rr = 0; rr < 15; ++rr) {
        // L2 prefetch 4 rows ahead (in-bounds: r0+rr+4 <= 127 when rr < 12)
        if (rr < 12)
            asm volatile("prefetch.global.L2 [%0];" :: "l"(rowp + 4 * WW));
        Cq = *(const float4*)(rowp + WW);
        rowp += WW;
        NMS_BODY(rr);
    }
    // row 15: next row exists only for warps 0..6 (warp-uniform branch)
    if (warp < 7) Cq = *(const float4*)(rowp + WW);
    else          Cq = make_float4(NEG, NEG, NEG, NEG);
    NMS_BODY(15);
#undef NMS_BODY

    // --- One deferred append per thread (+ round-1 histogram) ---------------
    {
        int n = __popcll(pk);
        int incl = n;
        #pragma unroll
        for (int o = 1; o < 32; o <<= 1) {
            int x = __shfl_up_sync(0xFFFFFFFFu, incl, o);
            if (lane >= o) incl += x;
        }
        int wtot = __shfl_sync(0xFFFFFFFFu, incl, 31);
        int base = 0;
        if (lane == 31 && wtot) base = atomicAdd(&s_ncand, wtot);
        base = __shfl_sync(0xFFFFFFFFu, base, 31);
        int pos = base + incl - n;

        const int cbase = r0 * WW + (lane << 2);
        unsigned long long m = pk;
        while (m) {
            int bit = __ffsll((long long)m) - 1;
            m &= m - 1ULL;
            int idx = cbase + ((bit >> 2) * WW) + (bit & 3);
            unsigned vb = __float_as_uint(__ldg(&t[idx]));
            if (pos < CAND_CAP) {
                s_sc[pos]  = vb;
                s_idx[pos] = (unsigned)idx;
                atomicAdd(&s_hist[vb >> 24], 1);
            }
            pos++;
        }
    }
    __syncthreads();
    int ncand = min(s_ncand, CAND_CAP);

    // --- Pathological fallback: <100 peaks -> append zero-score non-peaks ---
    if (ncand < K) {
        int idx = tid;                     // first 256 cells contain the 100
        int r = idx >> 7, c = idx & (WW - 1);
        float v = t[idx];
        float mval = v;
        for (int dr = -1; dr <= 1; ++dr)
            for (int dc = -1; dc <= 1; ++dc) {
                int rr2 = r + dr, cc = c + dc;
                if (rr2 >= 0 && rr2 < HH && cc >= 0 && cc < WW)
                    mval = fmaxf(mval, t[rr2 * WW + cc]);
            }
        if (mval != v) {   // suppressed: value 0 after keep-mask
            int p = atomicAdd(&s_ncand, 1);
            if (p < CAND_CAP) {
                s_sc[p]  = 0u;
                s_idx[p] = (unsigned)idx;
                atomicAdd(&s_hist[0], 1);
            }
        }
        __syncthreads();
        ncand = min(s_ncand, CAND_CAP);
    }

    // --- Radix-select on u32 score: floor Ts, count(>=Ts) in [K, FINAL_CAP] -
    unsigned Ts;
    {
        int need = K;
        int total_above = 0;
        unsigned prefix = 0;
        int shift = 24;                    // round-1 histogram already built
        for (;;) {
            suffix_scan_store(s_hist, s_scan, s_red, tid, lane, warp);
            {
                int d = tid;
                int suf  = s_scan[255 - d];
                int suf1 = (d == 255) ? 0 : s_scan[254 - d];
                if (suf >= need && suf1 < need) s_sel = d;
            }
            __syncthreads();
            int dsel  = s_sel;
            int A     = (dsel == 255) ? 0 : s_scan[254 - dsel];
            int inbin = s_scan[255 - dsel] - A;
            prefix = (prefix << 8) | (unsigned)dsel;
            total_above += A;
            need -= A;
            if (total_above + inbin <= FINAL_CAP || shift == 0) {
                Ts = prefix << shift;
                break;
            }
            shift -= 8;
            __syncthreads();               // protect s_scan/s_sel
            s_hist[tid] = 0;
            __syncthreads();
            for (int i = tid; i < ncand; i += 256) {
                unsigned sb = s_sc[i];
                if ((sb >> (shift + 8)) == prefix)
                    atomicAdd(&s_hist[(sb >> shift) & 255u], 1);
            }
            __syncthreads();
        }
    }
    __syncthreads();

    // --- Collect survivors (<=256) as u64 keys and rank-emit ----------------
    for (int i = tid; i < ncand; i += 256) {
        unsigned sb = s_sc[i];
        if (sb >= Ts) {
            int p = atomicAdd(&s_nfinal, 1);
            if (p < FINAL_CAP)
                s_final[p] = ((unsigned long long)sb << 32) | (unsigned)(~s_idx[i]);
        }
    }
    __syncthreads();
    {
        int nf = min(s_nfinal, FINAL_CAP);
        if (tid < nf) {
            unsigned long long my = s_final[tid];
            int rank = 0;
            #pragma unroll 4
            for (int i = 0; i < nf; ++i) rank += (s_final[i] > my) ? 1 : 0;
            if (rank < K) {
                out[OFF_SC + bc * K + rank] = __uint_as_float((unsigned)(my >> 32));
                g_idx1[bc * K + rank] = (int)(~(unsigned)my);
            }
        }
    }

    // --- Batch completion: last CTA of batch b runs stage2 inline -----------
    __threadfence();
    __syncthreads();
    if (tid == 0) {
        int v = atomicAdd(&g_done[b], 1);
        s_last = (v == CLS - 1) ? 1 : 0;
        if (v == CLS - 1) atomicExch(&g_done[b], 0);   // reset for graph replay
    }
    __syncthreads();
    if (!s_last) return;
    __threadfence();

    // ======================= Inline stage 2 for batch b ======================
    const int NC     = CLS * K;                        // 8000
    const int NCACHE = 2 * CAND_CAP;                   // 6144 u32 cache slots
    const float* __restrict__ sc = out + OFF_SC + (size_t)b * NC;

    s_hist[tid] = 0;
    if (tid == 0) s_nfinal = 0;
    __syncthreads();

    // load + round-1 histogram in one pass
    for (int i = tid; i < NC; i += 256) {
        unsigned sb = __float_as_uint(__ldg(&sc[i]));
        if (i < NCACHE) s_pool[i] = sb;
        atomicAdd(&s_hist[sb >> 24], 1);
    }
    __syncthreads();

    unsigned Ts2;
    {
        int need = K;
        int total_above = 0;
        unsigned prefix = 0;
        int shift = 24;
        for (;;) {
            suffix_scan_store(s_hist, s_scan, s_red, tid, lane, warp);
            {
                int d = tid;
                int suf  = s_scan[255 - d];
                int suf1 = (d == 255) ? 0 : s_scan[254 - d];
                if (suf >= need && suf1 < need) s_sel = d;
            }
            __syncthreads();
            int dsel  = s_sel;
            int A     = (dsel == 255) ? 0 : s_scan[254 - dsel];
            int inbin = s_scan[255 - dsel] - A;
            prefix = (prefix << 8) | (unsigned)dsel;
            total_above += A;
            need -= A;
            if (total_above + inbin <= FINAL_CAP || shift == 0) {
                Ts2 = prefix << shift;
                break;
            }
            shift -= 8;
            __syncthreads();
            s_hist[tid] = 0;
            __syncthreads();
            for (int i = tid; i < NC; i += 256) {
                unsigned sb = (i < NCACHE) ? s_pool[i]
                                           : __float_as_uint(__ldg(&sc[i]));
                if ((sb >> (shift + 8)) == prefix)
                    atomicAdd(&s_hist[(sb >> shift) & 255u], 1);
            }
            __syncthreads();
        }
    }
    __syncthreads();

    for (int i = tid; i < NC; i += 256) {
        unsigned sb = (i < NCACHE) ? s_pool[i] : __float_as_uint(__ldg(&sc[i]));
        if (sb >= Ts2) {
            int p = atomicAdd(&s_nfinal, 1);
            if (p < FINAL_CAP)
                s_final[p] = ((unsigned long long)sb << 32) | (unsigned)(~(unsigned)i);
        }
    }
    __syncthreads();
    {
        int nf = min(s_nfinal, FINAL_CAP);
        if (tid < nf) {
            unsigned long long my = s_final[tid];
            int rank = 0;
            #pragma unroll 4
            for (int i = 0; i < nf; ++i) rank += (s_final[i] > my) ? 1 : 0;
            if (rank < K) {
                int ci     = (int)(~(unsigned)my);           // combined idx [0,8000)
                int classe = ci / K;
                int flat   = g_idx1[b * NC + ci];
                out[OFF_IND  + b * K + rank] = (float)flat;
                out[OFF_CLSO + b * K + rank] = (float)classe;
                out[OFF_YS   + b * K + rank] = (float)(flat >> 7);   // y = flat / 128
                out[OFF_XS   + b * K + rank] = (float)(flat & 127);  // x = flat % 128
            }
        }
    }
}

// ---------------------------------------------------------------------------
extern "C" void kernel_launch(void* const* d_in, const int* in_sizes, int n_in,
                              void* d_out, int out_size)
{
    const float* hm = (const float*)d_in[0];
    float* out = (float*)d_out;
    decode_kernel<<<BS * CLS, 256>>>(hm, out);
}